// round 8
// baseline (speedup 1.0000x reference)
#include <cuda_runtime.h>

// Problem constants
#define BATCH   4
#define NQ      1024
#define NJ      2048
#define NJ2     1024
#define DMODEL  768
#define HEADS   12
#define DHEAD   64
#define INNER   768
#define SCALE   0.125f

// ---------------------------------------------------------------------------
// Scratch: packed bf16x2 hi/lo words. word(r,k2) = {elem(2k2) low16, elem(2k2+1) high16}
// All GEMM B operands are BT layout: [N][K/2 words].
// ---------------------------------------------------------------------------
__device__ unsigned g_xch[(size_t)BATCH * NJ * (DMODEL/2)];     // A: concat(x,ctx)
__device__ unsigned g_xcl[(size_t)BATCH * NJ * (DMODEL/2)];
__device__ unsigned g_wqth[INNER * (DMODEL/2)];                 // B: Wq^T
__device__ unsigned g_wqtl[INNER * (DMODEL/2)];
__device__ unsigned g_wkvth[2 * INNER * (DMODEL/2)];            // B: Wkv^T
__device__ unsigned g_wkvtl[2 * INNER * (DMODEL/2)];
__device__ unsigned g_woutth[DMODEL * (INNER/2)];               // B: Wout^T
__device__ unsigned g_wouttl[DMODEL * (INNER/2)];
__device__ unsigned g_qh[BATCH * NQ * (INNER/2)];               // A: q
__device__ unsigned g_ql[BATCH * NQ * (INNER/2)];
__device__ float    g_kv[(size_t)BATCH * NJ * 2 * INNER];       // fp32 kv
__device__ unsigned g_kh[(size_t)BATCH * NJ * (INNER/2)];       // B: k  [j][dh2]
__device__ unsigned g_kl[(size_t)BATCH * NJ * (INNER/2)];
__device__ unsigned g_vth[(size_t)BATCH * INNER * NJ2];         // B: v^T [hd][j2]
__device__ unsigned g_vtl[(size_t)BATCH * INNER * NJ2];
__device__ float    g_dots[(size_t)BATCH * NQ * HEADS * NJ];    // fp32 logits
__device__ unsigned g_ath[(size_t)BATCH * NQ * HEADS * NJ2];    // A: attn
__device__ unsigned g_atl[(size_t)BATCH * NQ * HEADS * NJ2];
__device__ unsigned g_aoh[BATCH * NQ * (INNER/2)];              // A: attn-out
__device__ unsigned g_aol[BATCH * NQ * (INNER/2)];

// ---------------------------------------------------------------------------
// Helpers
// ---------------------------------------------------------------------------
__device__ __forceinline__ unsigned pk(float e, float o) {   // low=e, high=o
    unsigned d;
    asm("cvt.rn.bf16x2.f32 %0, %1, %2;" : "=r"(d) : "f"(o), "f"(e));
    return d;
}
__device__ __forceinline__ float lo_f(unsigned w) { return __uint_as_float(w << 16); }
__device__ __forceinline__ float hi_f(unsigned w) { return __uint_as_float(w & 0xffff0000u); }
__device__ __forceinline__ void split2(float e, float o, unsigned& h, unsigned& l) {
    h = pk(e, o);
    l = pk(e - lo_f(h), o - hi_f(h));
}

__device__ __forceinline__ void mma_bf16(float* c, const unsigned* a, unsigned b0, unsigned b1) {
    asm volatile(
        "mma.sync.aligned.m16n8k16.row.col.f32.bf16.bf16.f32 "
        "{%0,%1,%2,%3},{%4,%5,%6,%7},{%8,%9},{%0,%1,%2,%3};"
        : "+f"(c[0]), "+f"(c[1]), "+f"(c[2]), "+f"(c[3])
        : "r"(a[0]), "r"(a[1]), "r"(a[2]), "r"(a[3]), "r"(b0), "r"(b1));
}

__device__ __forceinline__ void ldm4(unsigned* r, unsigned addr) {
    asm volatile("ldmatrix.sync.aligned.m8n8.x4.shared.b16 {%0,%1,%2,%3}, [%4];"
        : "=r"(r[0]), "=r"(r[1]), "=r"(r[2]), "=r"(r[3]) : "r"(addr));
}

__device__ __forceinline__ void cp16(void* smem_dst, const void* gsrc) {
    unsigned d = (unsigned)__cvta_generic_to_shared(smem_dst);
    asm volatile("cp.async.cg.shared.global [%0], [%1], 16;" :: "r"(d), "l"(gsrc));
}
__device__ __forceinline__ void cp_commit() { asm volatile("cp.async.commit_group;"); }
template<int N>
__device__ __forceinline__ void cp_wait() { asm volatile("cp.async.wait_group %0;" :: "n"(N)); }

// ---------------------------------------------------------------------------
// Pack kernels
// ---------------------------------------------------------------------------
// pack along columns (contiguous): dst[r][c2] = {src[r][2c2], src[r][2c2+1]}
__global__ void pack_cols_g(const float* __restrict__ src, long srs,
                            unsigned* __restrict__ dh, unsigned* __restrict__ dl,
                            long drs, int g8pr, long total) {
    long id = (long)blockIdx.x * blockDim.x + threadIdx.x;
    if (id >= total) return;
    int c8 = (int)(id % g8pr);
    long r  = id / g8pr;
    const float* s = src + r * srs + (long)c8 * 8;
    float4 v0 = *(const float4*)s;
    float4 v1 = *(const float4*)(s + 4);
    unsigned h[4], l[4];
    split2(v0.x, v0.y, h[0], l[0]);
    split2(v0.z, v0.w, h[1], l[1]);
    split2(v1.x, v1.y, h[2], l[2]);
    split2(v1.z, v1.w, h[3], l[3]);
    long o = r * drs + (long)c8 * 4;
    *(uint4*)(dh + o) = make_uint4(h[0], h[1], h[2], h[3]);
    *(uint4*)(dl + o) = make_uint4(l[0], l[1], l[2], l[3]);
}

// tiled transpose-pack: src fp32 [R][C] (row stride srs) -> dst words [C][R/2]
// dst[c][r2] = {src[2r2][c], src[2r2+1][c]}.  Grid: (R/64, C/64, Z), block 256.
__global__ void packT(const float* __restrict__ src, long srs, long szs,
                      unsigned* __restrict__ dh, unsigned* __restrict__ dl,
                      long drs, long dzs) {
    __shared__ float t[64][65];
    const float* s = src + (long)blockIdx.z * szs;
    const int r0 = blockIdx.x * 64, c0 = blockIdx.y * 64;
    const int tid = threadIdx.x;
    const int rr = tid / 16, c4 = (tid % 16) * 4;
#pragma unroll
    for (int i = 0; i < 4; i++) {
        float4 v = *(const float4*)(s + (long)(r0 + rr + i * 16) * srs + c0 + c4);
        t[rr + i * 16][c4 + 0] = v.x;
        t[rr + i * 16][c4 + 1] = v.y;
        t[rr + i * 16][c4 + 2] = v.z;
        t[rr + i * 16][c4 + 3] = v.w;
    }
    __syncthreads();
    unsigned* oh = dh + (long)blockIdx.z * dzs;
    unsigned* ol = dl + (long)blockIdx.z * dzs;
    const int c = tid / 32, k2 = tid % 32;
#pragma unroll
    for (int i = 0; i < 8; i++) {
        int cc = c + i * 8;
        unsigned h, l;
        split2(t[2 * k2][cc], t[2 * k2 + 1][cc], h, l);
        long o = (long)(c0 + cc) * drs + r0 / 2 + k2;
        oh[o] = h;
        ol[o] = l;
    }
}

// pack concat(x, context) along d
__global__ void pack_xc(const float* __restrict__ x, const float* __restrict__ ctx,
                        unsigned* __restrict__ dh, unsigned* __restrict__ dl) {
    long id = (long)blockIdx.x * blockDim.x + threadIdx.x;   // 786432
    int c8 = (int)(id % 96);
    long rj = id / 96;
    int j = (int)(rj % NJ);
    int b = (int)(rj / NJ);
    const float* src = (j < NQ) ? x   + ((long)b * NQ + j)      * DMODEL
                                : ctx + ((long)b * NQ + j - NQ) * DMODEL;
    float4 v0 = *(const float4*)(src + c8 * 8);
    float4 v1 = *(const float4*)(src + c8 * 8 + 4);
    unsigned h[4], l[4];
    split2(v0.x, v0.y, h[0], l[0]);
    split2(v0.z, v0.w, h[1], l[1]);
    split2(v1.x, v1.y, h[2], l[2]);
    split2(v1.z, v1.w, h[3], l[3]);
    long o = rj * 384 + (long)c8 * 4;
    *(uint4*)(dh + o) = make_uint4(h[0], h[1], h[2], h[3]);
    *(uint4*)(dl + o) = make_uint4(l[0], l[1], l[2], l[3]);
}

// ---------------------------------------------------------------------------
// bf16x3 GEMM, single BT path, ldmatrix fragment loads, 2-stage cp.async.
//   A: [M][K/2] words.  B: [N][K/2] words.  C: fp32 (+bias) or packed words.
// ---------------------------------------------------------------------------
struct GP {
    const unsigned *Ah, *Al, *Bh, *Bl;
    float* C;
    unsigned *Ch, *Cl;
    const float* bias;
    int K;
    int ldaw, ldbw, ldc;
    int Z2;
    long as1, as2, bs1, bs2, cs1, cs2;
    float alpha;
};

template<int BM, int BN, int WM, int WN, bool PACKO>
__global__ void __launch_bounds__(256, 2) bf16_gemm(GP p) {
    constexpr int WARPS_M = BM / WM;
    constexpr int WARPS_N = BN / WN;
    static_assert(WARPS_M * WARPS_N == 8, "256 threads");
    constexpr int MT  = WM / 16;
    constexpr int NTL = WN / 8;
    constexpr int A_SZ = BM * 20;     // words per array per stage
    constexpr int B_SZ = BN * 20;
    constexpr int STW  = 2 * (A_SZ + B_SZ);
    constexpr int A_CH = BM * 4 / 256;
    constexpr int B_CH = BN * 4 / 256;

    extern __shared__ unsigned sm[];
    const unsigned sbase = (unsigned)__cvta_generic_to_shared(sm);

    const int z  = blockIdx.z;
    const int z1 = z / p.Z2;
    const int z2 = z - z1 * p.Z2;
    const unsigned* gAh = p.Ah + z1 * p.as1 + z2 * p.as2;
    const unsigned* gAl = p.Al + z1 * p.as1 + z2 * p.as2;
    const unsigned* gBh = p.Bh + z1 * p.bs1 + z2 * p.bs2;
    const unsigned* gBl = p.Bl + z1 * p.bs1 + z2 * p.bs2;

    const int m0 = blockIdx.y * BM;
    const int n0 = blockIdx.x * BN;
    const int tid  = threadIdx.x;
    const int wid  = tid >> 5;
    const int lane = tid & 31;
    const int wm = wid % WARPS_M;
    const int wn = wid / WARPS_M;
    const int g = lane >> 2;
    const int t = lane & 3;

    // ldmatrix per-lane offsets (tile-row, k-word) — see fragment mapping notes
    const int a_ro = (lane & 7) + ((lane >> 3) & 1) * 8;
    const int a_ko = ((lane >> 4) & 1) * 4;
    const int b_ro = (lane & 7) + ((lane >> 4) & 1) * 8;
    const int b_ko = ((lane >> 3) & 1) * 4;

    float acc[MT][NTL][4];
#pragma unroll
    for (int mi = 0; mi < MT; mi++)
#pragma unroll
        for (int ni = 0; ni < NTL; ni++)
#pragma unroll
            for (int e = 0; e < 4; e++) acc[mi][ni][e] = 0.0f;

    auto issue = [&](int s) {
        unsigned* base = sm + (s & 1) * STW;
        unsigned* Ah = base;
        unsigned* Al = base + A_SZ;
        unsigned* Bh = base + 2 * A_SZ;
        unsigned* Bl = Bh + B_SZ;
        const int k0w = s * 16;
#pragma unroll
        for (int i = 0; i < A_CH; i++) {
            int c = tid + i * 256;
            int row = c >> 2;
            int cw  = (c & 3) << 2;
            long go = (long)(m0 + row) * p.ldaw + k0w + cw;
            cp16(Ah + row * 20 + cw, gAh + go);
            cp16(Al + row * 20 + cw, gAl + go);
        }
#pragma unroll
        for (int i = 0; i < B_CH; i++) {
            int c = tid + i * 256;
            int row = c >> 2;
            int cw  = (c & 3) << 2;
            long go = (long)(n0 + row) * p.ldbw + k0w + cw;
            cp16(Bh + row * 20 + cw, gBh + go);
            cp16(Bl + row * 20 + cw, gBl + go);
        }
    };

    const int S = p.K / 32;
    issue(0);
    cp_commit();

    for (int s = 0; s < S; s++) {
        if (s + 1 < S) {
            issue(s + 1);
            cp_commit();
            cp_wait<1>();
        } else {
            cp_wait<0>();
        }
        __syncthreads();

        const unsigned sA = sbase + ((s & 1) * STW) * 4;
        const unsigned sB = sA + 2 * A_SZ * 4;

#pragma unroll
        for (int ks = 0; ks < 2; ks++) {
            const int k2b = ks * 8;
            unsigned ah[MT][4], al[MT][4];
#pragma unroll
            for (int mi = 0; mi < MT; mi++) {
                unsigned addr = sA + ((unsigned)((wm * WM + mi * 16 + a_ro) * 20 + k2b + a_ko) << 2);
                ldm4(ah[mi], addr);
                ldm4(al[mi], addr + A_SZ * 4);
            }
#pragma unroll
            for (int np = 0; np < NTL / 2; np++) {
                unsigned addrB = sB + ((unsigned)((wn * WN + np * 16 + b_ro) * 20 + k2b + b_ko) << 2);
                unsigned bh[4], bl[4];
                ldm4(bh, addrB);
                ldm4(bl, addrB + B_SZ * 4);
#pragma unroll
                for (int mi = 0; mi < MT; mi++) {
                    mma_bf16(acc[mi][2 * np],     ah[mi], bh[0], bh[1]);
                    mma_bf16(acc[mi][2 * np],     ah[mi], bl[0], bl[1]);
                    mma_bf16(acc[mi][2 * np],     al[mi], bh[0], bh[1]);
                    mma_bf16(acc[mi][2 * np + 1], ah[mi], bh[2], bh[3]);
                    mma_bf16(acc[mi][2 * np + 1], ah[mi], bl[2], bl[3]);
                    mma_bf16(acc[mi][2 * np + 1], al[mi], bh[2], bh[3]);
                }
            }
        }
        __syncthreads();
    }

    // ---- epilogue ----
    if (PACKO) {
        unsigned* Ch = p.Ch + z1 * p.cs1 + z2 * p.cs2;
        unsigned* Cl = p.Cl + z1 * p.cs1 + z2 * p.cs2;
#pragma unroll
        for (int mi = 0; mi < MT; mi++) {
            int r0 = m0 + wm * WM + mi * 16 + g;
#pragma unroll
            for (int ni = 0; ni < NTL; ni++) {
                int cw = (n0 + wn * WN + ni * 8) / 2 + t;
                unsigned h, l;
                split2(acc[mi][ni][0] * p.alpha, acc[mi][ni][1] * p.alpha, h, l);
                Ch[(long)r0 * p.ldc + cw] = h;
                Cl[(long)r0 * p.ldc + cw] = l;
                split2(acc[mi][ni][2] * p.alpha, acc[mi][ni][3] * p.alpha, h, l);
                Ch[(long)(r0 + 8) * p.ldc + cw] = h;
                Cl[(long)(r0 + 8) * p.ldc + cw] = l;
            }
        }
    } else {
        float* C = p.C + z1 * p.cs1 + z2 * p.cs2;
#pragma unroll
        for (int mi = 0; mi < MT; mi++) {
            int r0 = m0 + wm * WM + mi * 16 + g;
#pragma unroll
            for (int ni = 0; ni < NTL; ni++) {
                int col = n0 + wn * WN + ni * 8 + t * 2;
                float bx = 0.f, by = 0.f;
                if (p.bias) { bx = p.bias[col]; by = p.bias[col + 1]; }
                float2 v0, v1;
                v0.x = acc[mi][ni][0] * p.alpha + bx;
                v0.y = acc[mi][ni][1] * p.alpha + by;
                v1.x = acc[mi][ni][2] * p.alpha + bx;
                v1.y = acc[mi][ni][3] * p.alpha + by;
                *(float2*)&C[(long)r0 * p.ldc + col]       = v0;
                *(float2*)&C[(long)(r0 + 8) * p.ldc + col] = v1;
            }
        }
    }
}

// ---------------------------------------------------------------------------
// Talking-heads softmax: 1024 threads, 2 j-cols/thread (occupancy 2x).
// premix -> softmax -> postmix; writes packed bf16 attn.
// ---------------------------------------------------------------------------
__global__ void __launch_bounds__(1024) mix_softmax4(
    const float* __restrict__ dots,
    unsigned* __restrict__ ath, unsigned* __restrict__ atl,
    const float* __restrict__ pre_g,
    const float* __restrict__ post_g)
{
    __shared__ float s_pre[HEADS * HEADS], s_post[HEADS * HEADS];
    __shared__ float red[32][HEADS];
    __shared__ float bm[HEADS], bs[HEADS];

    const int tid = threadIdx.x;
    if (tid < HEADS * HEADS) { s_pre[tid] = pre_g[tid]; s_post[tid] = post_g[tid]; }
    __syncthreads();

    const long base   = (long)blockIdx.x * (HEADS * NJ);
    const long base_w = (long)blockIdx.x * (HEADS * NJ2);
    const int j0 = tid * 2;
    const int w = tid >> 5, lane = tid & 31;

    float2 mx[HEADS];
#pragma unroll
    for (int gg = 0; gg < HEADS; gg++) mx[gg] = make_float2(0.f, 0.f);
#pragma unroll
    for (int h = 0; h < HEADS; h++) {
        float2 r = *(const float2*)(dots + base + (long)h * NJ + j0);
#pragma unroll
        for (int gg = 0; gg < HEADS; gg++) {
            float wv = s_pre[h * HEADS + gg];
            mx[gg].x += r.x * wv;
            mx[gg].y += r.y * wv;
        }
    }

    float m[HEADS];
#pragma unroll
    for (int gg = 0; gg < HEADS; gg++) m[gg] = fmaxf(mx[gg].x, mx[gg].y);
#pragma unroll
    for (int gg = 0; gg < HEADS; gg++)
#pragma unroll
        for (int o = 16; o; o >>= 1)
            m[gg] = fmaxf(m[gg], __shfl_xor_sync(0xFFFFFFFFu, m[gg], o));
#pragma unroll
    for (int gg = 0; gg < HEADS; gg++)
        if (lane == gg) red[w][gg] = m[gg];
    __syncthreads();
    if (tid < HEADS) {
        float mm = -1e30f;
#pragma unroll
        for (int ww = 0; ww < 32; ww++) mm = fmaxf(mm, red[ww][tid]);
        bm[tid] = mm;
    }
    __syncthreads();

    float s[HEADS];
#pragma unroll
    for (int gg = 0; gg < HEADS; gg++) {
        float mm = bm[gg];
        mx[gg].x = __expf(mx[gg].x - mm);
        mx[gg].y = __expf(mx[gg].y - mm);
        s[gg] = mx[gg].x + mx[gg].y;
    }
#pragma unroll
    for (int gg = 0; gg < HEADS; gg++)
#pragma unroll
        for (int o = 16; o; o >>= 1)
            s[gg] += __shfl_xor_sync(0xFFFFFFFFu, s[gg], o);
    __syncthreads();
#pragma unroll
    for (int gg = 0; gg < HEADS; gg++)
        if (lane == gg) red[w][gg] = s[gg];
    __syncthreads();
    if (tid < HEADS) {
        float ss = 0.f;
#pragma unroll
        for (int ww = 0; ww < 32; ww++) ss += red[ww][tid];
        bs[tid] = ss;
    }
    __syncthreads();

#pragma unroll
    for (int gg = 0; gg < HEADS; gg++) {
        float inv = 1.0f / bs[gg];
        mx[gg].x *= inv;
        mx[gg].y *= inv;
    }

#pragma unroll
    for (int gg = 0; gg < HEADS; gg++) {
        float2 o = make_float2(0.f, 0.f);
#pragma unroll
        for (int h = 0; h < HEADS; h++) {
            float wv = s_post[h * HEADS + gg];
            o.x += mx[h].x * wv;
            o.y += mx[h].y * wv;
        }
        unsigned hw, lw;
        split2(o.x, o.y, hw, lw);
        long idx = base_w + (long)gg * NJ2 + tid;
        ath[idx] = hw;
        atl[idx] = lw;
    }
}

// ---------------------------------------------------------------------------
// Launch
// ---------------------------------------------------------------------------
#define SMEM_128  (2 * 2 * (128*20 + 128*20) * 4)   // 81920
#define SMEM_64   (2 * 2 * (128*20 +  64*20) * 4)   // 61440

extern "C" void kernel_launch(void* const* d_in, const int* in_sizes, int n_in,
                              void* d_out, int out_size) {
    (void)in_sizes; (void)n_in; (void)out_size;
    const float* x        = (const float*)d_in[0];
    const float* context  = (const float*)d_in[1];
    const float* Wq       = (const float*)d_in[2];
    const float* Wkv      = (const float*)d_in[3];
    const float* mix_pre  = (const float*)d_in[4];
    const float* mix_post = (const float*)d_in[5];
    const float* Wout     = (const float*)d_in[6];
    const float* b_out    = (const float*)d_in[7];
    float* out = (float*)d_out;

    unsigned *xch, *xcl, *wqth, *wqtl, *wkvth, *wkvtl, *woutth, *wouttl;
    unsigned *qh, *ql, *kh, *kl, *vth, *vtl, *ath, *atl, *aoh, *aol;
    float *kv, *dots;
    cudaGetSymbolAddress((void**)&xch, g_xch);     cudaGetSymbolAddress((void**)&xcl, g_xcl);
    cudaGetSymbolAddress((void**)&wqth, g_wqth);   cudaGetSymbolAddress((void**)&wqtl, g_wqtl);
    cudaGetSymbolAddress((void**)&wkvth, g_wkvth); cudaGetSymbolAddress((void**)&wkvtl, g_wkvtl);
    cudaGetSymbolAddress((void**)&woutth, g_woutth); cudaGetSymbolAddress((void**)&wouttl, g_wouttl);
    cudaGetSymbolAddress((void**)&qh, g_qh);       cudaGetSymbolAddress((void**)&ql, g_ql);
    cudaGetSymbolAddress((void**)&kh, g_kh);       cudaGetSymbolAddress((void**)&kl, g_kl);
    cudaGetSymbolAddress((void**)&vth, g_vth);     cudaGetSymbolAddress((void**)&vtl, g_vtl);
    cudaGetSymbolAddress((void**)&ath, g_ath);     cudaGetSymbolAddress((void**)&atl, g_atl);
    cudaGetSymbolAddress((void**)&aoh, g_aoh);     cudaGetSymbolAddress((void**)&aol, g_aol);
    cudaGetSymbolAddress((void**)&kv, g_kv);       cudaGetSymbolAddress((void**)&dots, g_dots);

    cudaFuncSetAttribute(bf16_gemm<128,128,32,64,true>,
                         cudaFuncAttributeMaxDynamicSharedMemorySize, SMEM_128);
    cudaFuncSetAttribute(bf16_gemm<128,128,32,64,false>,
                         cudaFuncAttributeMaxDynamicSharedMemorySize, SMEM_128);
    cudaFuncSetAttribute(bf16_gemm<128,64,32,32,true>,
                         cudaFuncAttributeMaxDynamicSharedMemorySize, SMEM_64);

    // ---- pack inputs ----
    pack_xc<<<3072, 256>>>(x, context, xch, xcl);
    packT<<<dim3(12, 12, 1), 256>>>(Wq,   INNER,   0, wqth,  wqtl,  DMODEL/2, 0);
    packT<<<dim3(12, 24, 1), 256>>>(Wkv,  2*INNER, 0, wkvth, wkvtl, DMODEL/2, 0);
    packT<<<dim3(12, 12, 1), 256>>>(Wout, DMODEL,  0, woutth, wouttl, INNER/2, 0);

    // K1: q = xc[:NQ] @ Wq  -> packed q
    {
        GP p = {};
        p.Ah = xch; p.Al = xcl; p.Bh = wqth; p.Bl = wqtl;
        p.Ch = qh; p.Cl = ql;
        p.K = DMODEL; p.ldaw = DMODEL/2; p.ldbw = DMODEL/2; p.ldc = INNER/2;
        p.Z2 = 1;
        p.as1 = (long)NJ * (DMODEL/2);
        p.cs1 = (long)NQ * (INNER/2);
        p.alpha = 1.0f;
        bf16_gemm<128,128,32,64,true>
            <<<dim3(INNER/128, NQ/128, BATCH), 256, SMEM_128>>>(p);
    }
    // K2: kv = xc @ Wkv  -> fp32
    {
        GP p = {};
        p.Ah = xch; p.Al = xcl; p.Bh = wkvth; p.Bl = wkvtl;
        p.C = kv;
        p.K = DMODEL; p.ldaw = DMODEL/2; p.ldbw = DMODEL/2; p.ldc = 2*INNER;
        p.Z2 = 1;
        p.as1 = (long)NJ * (DMODEL/2);
        p.cs1 = (long)NJ * 2 * INNER;
        p.alpha = 1.0f;
        bf16_gemm<128,128,32,64,false>
            <<<dim3(2*INNER/128, NJ/128, BATCH), 256, SMEM_128>>>(p);
    }
    // pack k (cols) and v (transpose)
    pack_cols_g<<<3072, 256>>>(kv, 2*INNER, kh, kl, INNER/2, INNER/8,
                               (long)BATCH * NJ * (INNER/8));
    packT<<<dim3(NJ/64, INNER/64, BATCH), 256>>>(kv + INNER, 2*INNER,
                                                 (long)NJ * 2 * INNER,
                                                 vth, vtl, NJ2, (long)INNER * NJ2);

    // K3: dots = SCALE * q @ k^T  (48 batch-heads) -> fp32
    {
        GP p = {};
        p.Ah = qh; p.Al = ql; p.Bh = kh; p.Bl = kl;
        p.C = dots;
        p.K = DHEAD; p.ldaw = INNER/2; p.ldbw = INNER/2; p.ldc = HEADS*NJ;
        p.Z2 = HEADS;
        p.as1 = (long)NQ * (INNER/2); p.as2 = DHEAD/2;
        p.bs1 = (long)NJ * (INNER/2); p.bs2 = DHEAD/2;
        p.cs1 = (long)NQ * HEADS * NJ; p.cs2 = NJ;
        p.alpha = SCALE;
        bf16_gemm<128,128,32,64,false>
            <<<dim3(NJ/128, NQ/128, BATCH*HEADS), 256, SMEM_128>>>(p);
    }
    // K4: talking-heads softmax -> packed attn
    mix_softmax4<<<BATCH * NQ, 1024>>>(dots, ath, atl, mix_pre, mix_post);
    // K5: ao = attn @ v  (48 batch-heads) -> packed ao
    {
        GP p = {};
        p.Ah = ath; p.Al = atl; p.Bh = vth; p.Bl = vtl;
        p.Ch = aoh; p.Cl = aol;
        p.K = NJ; p.ldaw = HEADS*NJ2; p.ldbw = NJ2; p.ldc = INNER/2;
        p.Z2 = HEADS;
        p.as1 = (long)NQ * HEADS * NJ2; p.as2 = NJ2;
        p.bs1 = (long)INNER * NJ2;      p.bs2 = (long)DHEAD * NJ2;
        p.cs1 = (long)NQ * (INNER/2);   p.cs2 = DHEAD/2;
        p.alpha = 1.0f;
        bf16_gemm<128,64,32,32,true>
            <<<dim3(1, NQ/128, BATCH*HEADS), 256, SMEM_64>>>(p);
    }
    // K6: out = ao @ Wout + b_out  -> fp32
    {
        GP p = {};
        p.Ah = aoh; p.Al = aol; p.Bh = woutth; p.Bl = wouttl;
        p.C = out; p.bias = b_out;
        p.K = INNER; p.ldaw = INNER/2; p.ldbw = INNER/2; p.ldc = DMODEL;
        p.Z2 = 1;
        p.alpha = 1.0f;
        bf16_gemm<128,128,32,64,false>
            <<<dim3(DMODEL/128, (BATCH*NQ)/128, 1), 256, SMEM_128>>>(p);
    }
}